// round 1
// baseline (speedup 1.0000x reference)
#include <cuda_runtime.h>
#include <math.h>

#define NN 10000
#define EE 160000
#define GG 64
#define HH 4
#define EDIM 32

// ---------------- static scratch (no allocations allowed) ----------------
__device__ int   g_deg[NN];
__device__ int   g_rowptr[NN + 1];
__device__ int   g_cursor[NN];
__device__ int   g_eperm[EE];
__device__ float g_xs[(size_t)NN * 1024];   // max H*C = 4*256
__device__ float g_hA[(size_t)NN * 256];
__device__ float g_hB[(size_t)NN * 256];
__device__ float g_alsrc[NN * HH];
__device__ float g_aldst[NN * HH];
__device__ float g_ale[(size_t)EE * HH];
__device__ float g_expw[(size_t)EE * HH];
__device__ float g_loopexp[NN * HH];
__device__ float g_invsum[NN * HH];
__device__ float g_M[EDIM * HH];
__device__ int   g_gcnt[GG];

// ---------------- CSR build ----------------
__global__ void k_deg(const int* __restrict__ dst) {
    int e = blockIdx.x * blockDim.x + threadIdx.x;
    if (e < EE) atomicAdd(&g_deg[dst[e]], 1);
}

__global__ void k_scan() {
    __shared__ int sh[1024];
    __shared__ int carry;
    int tid = threadIdx.x;
    if (tid == 0) { carry = 0; g_rowptr[0] = 0; }
    __syncthreads();
    for (int base = 0; base < NN; base += 1024) {
        int i = base + tid;
        int v = (i < NN) ? g_deg[i] : 0;
        sh[tid] = v;
        __syncthreads();
        for (int off = 1; off < 1024; off <<= 1) {
            int t = (tid >= off) ? sh[tid - off] : 0;
            __syncthreads();
            sh[tid] += t;
            __syncthreads();
        }
        int inc = sh[tid];
        int cl = carry;
        if (i < NN) {
            g_rowptr[i + 1] = cl + inc;
            g_cursor[i] = cl + inc - v;
        }
        __syncthreads();
        if (tid == 0) carry = cl + sh[1023];
        __syncthreads();
    }
}

__global__ void k_scatter(const int* __restrict__ dst) {
    int e = blockIdx.x * blockDim.x + threadIdx.x;
    if (e < EE) {
        int p = atomicAdd(&g_cursor[dst[e]], 1);
        g_eperm[p] = e;
    }
}

// ---------------- GEMM: C[M,Ncol] = A[M,K] @ B[K,Ncol], fp32, tiled ----------------
#define BM 64
#define BN 64
#define BK 16
__global__ void k_gemm(const float* __restrict__ A, const float* __restrict__ B,
                       float* __restrict__ C, int M, int K, int Ncol) {
    __shared__ float As[BK][BM];
    __shared__ float Bs[BK][BN];
    int tid = threadIdx.x;            // 256 threads
    int tx = tid % 16, ty = tid / 16;
    int row0 = blockIdx.y * BM, col0 = blockIdx.x * BN;

    int ar = tid >> 2;                // 0..63
    int ak = (tid & 3) * 4;           // 0,4,8,12
    int bk = tid >> 4;                // 0..15
    int bc = (tid & 15) * 4;          // 0..60

    float acc[4][4];
#pragma unroll
    for (int i = 0; i < 4; i++)
#pragma unroll
        for (int j = 0; j < 4; j++) acc[i][j] = 0.f;

    for (int k0 = 0; k0 < K; k0 += BK) {
        float4 av = make_float4(0.f, 0.f, 0.f, 0.f);
        int arow = row0 + ar;
        if (arow < M) av = *(const float4*)(A + (size_t)arow * K + k0 + ak);
        As[ak + 0][ar] = av.x; As[ak + 1][ar] = av.y;
        As[ak + 2][ar] = av.z; As[ak + 3][ar] = av.w;

        float4 bv = *(const float4*)(B + (size_t)(k0 + bk) * Ncol + col0 + bc);
        *(float4*)&Bs[bk][bc] = bv;
        __syncthreads();
#pragma unroll
        for (int kk = 0; kk < BK; kk++) {
            float a[4], b[4];
#pragma unroll
            for (int i = 0; i < 4; i++) a[i] = As[kk][ty * 4 + i];
#pragma unroll
            for (int j = 0; j < 4; j++) b[j] = Bs[kk][tx * 4 + j];
#pragma unroll
            for (int i = 0; i < 4; i++)
#pragma unroll
                for (int j = 0; j < 4; j++) acc[i][j] += a[i] * b[j];
        }
        __syncthreads();
    }
#pragma unroll
    for (int i = 0; i < 4; i++) {
        int r = row0 + ty * 4 + i;
        if (r < M) {
#pragma unroll
            for (int j = 0; j < 4; j++)
                C[(size_t)r * Ncol + col0 + tx * 4 + j] = acc[i][j];
        }
    }
}

// ---------------- attention coefficients: al_src / al_dst ----------------
__global__ void k_attn(const float* __restrict__ xs, const float* __restrict__ a_s,
                       const float* __restrict__ a_d, int C) {
    int w = (blockIdx.x * blockDim.x + threadIdx.x) >> 5;
    int lane = threadIdx.x & 31;
    if (w >= NN * HH) return;
    int n = w / HH, h = w % HH;
    const float* xrow = xs + (size_t)n * HH * C + h * C;
    float s = 0.f, d = 0.f;
    for (int c = lane; c < C; c += 32) {
        float v = xrow[c];
        s += v * a_s[h * C + c];
        d += v * a_d[h * C + c];
    }
#pragma unroll
    for (int o = 16; o; o >>= 1) {
        s += __shfl_down_sync(0xffffffffu, s, o);
        d += __shfl_down_sync(0xffffffffu, d, o);
    }
    if (lane == 0) { g_alsrc[n * HH + h] = s; g_aldst[n * HH + h] = d; }
}

// ---------------- edge-attention weight contraction ----------------
__global__ void k_M(const float* __restrict__ We, const float* __restrict__ ae, int C) {
    int i = threadIdx.x;
    if (i >= EDIM * HH) return;
    int d = i / HH, h = i % HH;
    float s = 0.f;
    for (int c = 0; c < C; c++) s += We[(size_t)d * HH * C + h * C + c] * ae[h * C + c];
    g_M[d * HH + h] = s;
}

__global__ void k_ale(const float* __restrict__ eattr) {
    __shared__ float Ms[EDIM * HH];
    if (threadIdx.x < EDIM * HH) Ms[threadIdx.x] = g_M[threadIdx.x];
    __syncthreads();
    int e = blockIdx.x * blockDim.x + threadIdx.x;
    if (e >= EE) return;
    float a[HH] = {0.f, 0.f, 0.f, 0.f};
    const float4* ep = (const float4*)(eattr + (size_t)e * EDIM);
#pragma unroll
    for (int q = 0; q < EDIM / 4; q++) {
        float4 v = ep[q];
        int d = q * 4;
#pragma unroll
        for (int h = 0; h < HH; h++) {
            a[h] += v.x * Ms[(d + 0) * HH + h] + v.y * Ms[(d + 1) * HH + h]
                  + v.z * Ms[(d + 2) * HH + h] + v.w * Ms[(d + 3) * HH + h];
        }
    }
    float4 o = make_float4(a[0], a[1], a[2], a[3]);
    *(float4*)(g_ale + (size_t)e * HH) = o;
}

// ---------------- segment softmax (warp per dst node) ----------------
__device__ __forceinline__ float lrelu(float x) { return x >= 0.f ? x : 0.2f * x; }

__global__ void k_softmax(const int* __restrict__ src) {
    int n = (blockIdx.x * blockDim.x + threadIdx.x) >> 5;
    int lane = threadIdx.x & 31;
    if (n >= NN) return;
    int st = g_rowptr[n], en = g_rowptr[n + 1];
    float adst[HH], asrcn[HH];
#pragma unroll
    for (int h = 0; h < HH; h++) { adst[h] = g_aldst[n * HH + h]; asrcn[h] = g_alsrc[n * HH + h]; }

    float mx[HH] = {-1e30f, -1e30f, -1e30f, -1e30f};
    float sa[HH] = {0.f, 0.f, 0.f, 0.f};
    for (int j = st + lane; j < en; j += 32) {
        int e = g_eperm[j];
        int s = src[e];
#pragma unroll
        for (int h = 0; h < HH; h++) {
            float ale = g_ale[(size_t)e * HH + h];
            sa[h] += ale;
            float l = lrelu(g_alsrc[s * HH + h] + adst[h] + ale);
            mx[h] = fmaxf(mx[h], l);
        }
    }
#pragma unroll
    for (int h = 0; h < HH; h++)
#pragma unroll
        for (int o = 16; o; o >>= 1) {
            mx[h] = fmaxf(mx[h], __shfl_xor_sync(0xffffffffu, mx[h], o));
            sa[h] += __shfl_xor_sync(0xffffffffu, sa[h], o);
        }
    int deg = en - st;
    float inv = 1.f / (float)(deg > 0 ? deg : 1);
    float llog[HH];
#pragma unroll
    for (int h = 0; h < HH; h++) {
        float l = lrelu(asrcn[h] + adst[h] + sa[h] * inv);
        llog[h] = l;
        mx[h] = fmaxf(mx[h], l);
    }
    float se[HH] = {0.f, 0.f, 0.f, 0.f};
    for (int j = st + lane; j < en; j += 32) {
        int e = g_eperm[j];
        int s = src[e];
#pragma unroll
        for (int h = 0; h < HH; h++) {
            float l = lrelu(g_alsrc[s * HH + h] + adst[h] + g_ale[(size_t)e * HH + h]);
            float w = expf(l - mx[h]);
            g_expw[(size_t)e * HH + h] = w;
            se[h] += w;
        }
    }
#pragma unroll
    for (int h = 0; h < HH; h++)
#pragma unroll
        for (int o = 16; o; o >>= 1) se[h] += __shfl_xor_sync(0xffffffffu, se[h], o);
    if (lane == 0) {
#pragma unroll
        for (int h = 0; h < HH; h++) {
            float le = expf(llog[h] - mx[h]);
            g_loopexp[n * HH + h] = le;
            g_invsum[n * HH + h] = 1.f / (se[h] + le + 1e-16f);
        }
    }
}

// ---------------- aggregation (block per dst node) ----------------
__device__ __forceinline__ float pick4(float4 v, int h) {
    return h == 0 ? v.x : h == 1 ? v.y : h == 2 ? v.z : v.w;
}

template <int C>
__global__ void k_agg(const int* __restrict__ src, const float* __restrict__ xs,
                      const float* __restrict__ bias, float* __restrict__ hout) {
    constexpr int CH = HH * C;
    constexpr int K = CH / 128;
    int n = blockIdx.x;
    int t = threadIdx.x;
    int st = g_rowptr[n], en = g_rowptr[n + 1];
    float acc[K];
#pragma unroll
    for (int i = 0; i < K; i++) acc[i] = 0.f;

    for (int j = st; j < en; j++) {
        int e = g_eperm[j];
        int s = src[e];
        float4 w4 = *(const float4*)(g_expw + (size_t)e * HH);
        const float* xrow = xs + (size_t)s * CH;
#pragma unroll
        for (int i = 0; i < K; i++) {
            int h = (i * 128) / C;   // valid since t < 128
            acc[i] += pick4(w4, h) * xrow[t + i * 128];
        }
    }
    // self loop
    {
        float4 w4 = *(const float4*)(g_loopexp + (size_t)n * HH);
        const float* xrow = xs + (size_t)n * CH;
#pragma unroll
        for (int i = 0; i < K; i++) {
            int h = (i * 128) / C;
            acc[i] += pick4(w4, h) * xrow[t + i * 128];
        }
    }
    float4 is = *(const float4*)(g_invsum + (size_t)n * HH);
    if (C == 128) {
        float v = 0.25f * (acc[0] * is.x + acc[1] * is.y + acc[2] * is.z + acc[3] * is.w)
                + bias[t];
        v = v > 0.f ? v : expm1f(v);
        hout[(size_t)n * C + t] = v;
    } else {
        float v0 = 0.25f * (acc[0] * is.x + acc[2] * is.y + acc[4] * is.z + acc[6] * is.w)
                 + bias[t];
        float v1 = 0.25f * (acc[1] * is.x + acc[3] * is.y + acc[5] * is.z + acc[7] * is.w)
                 + bias[t + 128];
        v0 = v0 > 0.f ? v0 : expm1f(v0);
        v1 = v1 > 0.f ? v1 : expm1f(v1);
        hout[(size_t)n * C + t] = v0;
        hout[(size_t)n * C + t + 128] = v1;
    }
}

// ---------------- graph mean pooling ----------------
__global__ void k_gcnt(const int* __restrict__ batch) {
    int n = blockIdx.x * blockDim.x + threadIdx.x;
    if (n < NN) atomicAdd(&g_gcnt[batch[n]], 1);
}

__global__ void k_pool(const int* __restrict__ batch, const float* __restrict__ h,
                       float* __restrict__ out) {
    int n = blockIdx.x;
    int t = threadIdx.x;  // 128
    atomicAdd(&out[(size_t)batch[n] * 128 + t], h[(size_t)n * 128 + t]);
}

__global__ void k_pooldiv(float* __restrict__ out) {
    int i = blockIdx.x * blockDim.x + threadIdx.x;
    if (i < GG * 128) {
        int g = i / 128;
        int c = g_gcnt[g];
        out[i] /= (float)(c > 0 ? c : 1);
    }
}

// ---------------- launch ----------------
extern "C" void kernel_launch(void* const* d_in, const int* in_sizes, int n_in,
                              void* d_out, int out_size) {
    const float* x     = (const float*)d_in[0];
    const int*   ei    = (const int*)d_in[1];
    const float* eattr = (const float*)d_in[2];
    const int*   batch = (const int*)d_in[3];
    const int* src = ei;
    const int* dst = ei + EE;

    const float* W[3]  = {(const float*)d_in[4],  (const float*)d_in[10], (const float*)d_in[16]};
    const float* We[3] = {(const float*)d_in[5],  (const float*)d_in[11], (const float*)d_in[17]};
    const float* As[3] = {(const float*)d_in[6],  (const float*)d_in[12], (const float*)d_in[18]};
    const float* Ad[3] = {(const float*)d_in[7],  (const float*)d_in[13], (const float*)d_in[19]};
    const float* Ae[3] = {(const float*)d_in[8],  (const float*)d_in[14], (const float*)d_in[20]};
    const float* Bb[3] = {(const float*)d_in[9],  (const float*)d_in[15], (const float*)d_in[21]};

    float* out = (float*)d_out;

    void *p_deg, *p_gcnt;
    cudaGetSymbolAddress(&p_deg, g_deg);
    cudaGetSymbolAddress(&p_gcnt, g_gcnt);
    cudaMemsetAsync(p_deg, 0, NN * sizeof(int));
    cudaMemsetAsync(p_gcnt, 0, GG * sizeof(int));
    cudaMemsetAsync(out, 0, (size_t)GG * 128 * sizeof(float));

    // CSR build (same for all layers)
    k_deg<<<(EE + 255) / 256, 256>>>(dst);
    k_scan<<<1, 1024>>>();
    k_scatter<<<(EE + 255) / 256, 256>>>(dst);

    const int Kdim[3]  = {128, 128, 256};
    const int Cdim[3]  = {128, 256, 128};
    const float* Ain[3] = {x, g_hA, g_hB};  // device-symbol addresses resolved below
    // Device symbols used directly: taking their address on host is invalid,
    // so fetch real pointers.
    void *p_xs, *p_hA, *p_hB;
    cudaGetSymbolAddress(&p_xs, g_xs);
    cudaGetSymbolAddress(&p_hA, g_hA);
    cudaGetSymbolAddress(&p_hB, g_hB);
    float* xs = (float*)p_xs;
    float* hA = (float*)p_hA;
    float* hB = (float*)p_hB;
    const float* layer_in[3]  = {x, hA, hB};
    float*       layer_out[3] = {hA, hB, hA};
    (void)Ain; (void)n_in; (void)in_sizes; (void)out_size;

    for (int l = 0; l < 3; l++) {
        int Kd = Kdim[l], Cd = Cdim[l];
        int Ncol = HH * Cd;
        dim3 gg(Ncol / BN, (NN + BM - 1) / BM);
        k_gemm<<<gg, 256>>>(layer_in[l], W[l], xs, NN, Kd, Ncol);
        k_attn<<<(NN * HH * 32 + 255) / 256, 256>>>(xs, As[l], Ad[l], Cd);
        k_M<<<1, 128>>>(We[l], Ae[l], Cd);
        k_ale<<<(EE + 127) / 128, 128>>>(eattr);
        k_softmax<<<(NN * 32 + 255) / 256, 256>>>(src);
        if (Cd == 128)
            k_agg<128><<<NN, 128>>>(src, xs, Bb[l], layer_out[l]);
        else
            k_agg<256><<<NN, 128>>>(src, xs, Bb[l], layer_out[l]);
    }

    k_gcnt<<<(NN + 255) / 256, 256>>>(batch);
    k_pool<<<NN, 128>>>(batch, hA, out);
    k_pooldiv<<<(GG * 128 + 255) / 256, 256>>>(out);
}